// round 11
// baseline (speedup 1.0000x reference)
#include <cuda_runtime.h>
#include <cstdint>

// out[src[e]*16 + k] += attrs[k*E + e]   (attrs is feature-major (F,E); attr_idx int32)
// 16M RED.128 lane ops is the structural floor; this version restores occupancy
// (42% -> ~70%) by processing features in 4 chunks of 4 float4s (short live ranges)
// under __launch_bounds__(256, 6) so DRAM load latency hides behind RED issue.

__device__ __forceinline__ void red_add_v4(float* addr, float a, float b, float c, float d)
{
    asm volatile("red.global.add.v4.f32 [%0], {%1, %2, %3, %4};"
                 :: "l"(addr), "f"(a), "f"(b), "f"(c), "f"(d)
                 : "memory");
}

// Eq = E/4 (edge quads). attrs4 laid out as (16, Eq) float4.
__global__ __launch_bounds__(256, 6)
void scatter_sum_f16_q4(const float4* __restrict__ attrs4,
                        const int4* __restrict__ src4,
                        float* __restrict__ out,
                        int Eq, int out_size)
{
    int q = blockIdx.x * blockDim.x + threadIdx.x;
    if (q >= Eq) return;

    int4 n4 = __ldg(src4 + q);            // 4 consecutive src node ids

    float* o0 = ((unsigned)n4.x * 16u + 16u <= (unsigned)out_size) ? out + (size_t)n4.x * 16 : nullptr;
    float* o1 = ((unsigned)n4.y * 16u + 16u <= (unsigned)out_size) ? out + (size_t)n4.y * 16 : nullptr;
    float* o2 = ((unsigned)n4.z * 16u + 16u <= (unsigned)out_size) ? out + (size_t)n4.z * 16 : nullptr;
    float* o3 = ((unsigned)n4.w * 16u + 16u <= (unsigned)out_size) ? out + (size_t)n4.w * 16 : nullptr;

    // 4 chunks of 4 features: 16 live floats per chunk keeps regs ~40.
    #pragma unroll
    for (int c = 0; c < 4; c++) {
        float4 v0 = __ldg(attrs4 + (size_t)(4 * c + 0) * Eq + q);
        float4 v1 = __ldg(attrs4 + (size_t)(4 * c + 1) * Eq + q);
        float4 v2 = __ldg(attrs4 + (size_t)(4 * c + 2) * Eq + q);
        float4 v3 = __ldg(attrs4 + (size_t)(4 * c + 3) * Eq + q);

        int off = 4 * c;
        if (o0) red_add_v4(o0 + off, v0.x, v1.x, v2.x, v3.x);
        if (o1) red_add_v4(o1 + off, v0.y, v1.y, v2.y, v3.y);
        if (o2) red_add_v4(o2 + off, v0.z, v1.z, v2.z, v3.z);
        if (o3) red_add_v4(o3 + off, v0.w, v1.w, v2.w, v3.w);
    }
}

// Scalar fallback for F != 16 or E % 4 != 0.
__global__ void scatter_sum_scalar(const float* __restrict__ attrs,
                                   const int* __restrict__ src,
                                   float* __restrict__ out,
                                   int E, int F, int out_size)
{
    int e = blockIdx.x * blockDim.x + threadIdx.x;
    if (e >= E) return;
    int n = src[e];
    long long base = (long long)n * F;
    if (n < 0 || base + F > out_size) return;
    float* o = out + base;
    for (int k = 0; k < F; k++)
        atomicAdd(o + k, __ldg(attrs + (size_t)k * E + e));
}

extern "C" void kernel_launch(void* const* d_in, const int* in_sizes, int n_in,
                              void* d_out, int out_size)
{
    const float* attrs = (const float*)d_in[0];   // (E, F) buffer, used as (F, E)
    const int*   aidx  = (const int*)d_in[1];     // (2, E) int32; row 0 = src

    int E = in_sizes[1] / 2;
    int F = in_sizes[0] / E;

    float* out = (float*)d_out;

    cudaMemsetAsync(d_out, 0, (size_t)out_size * sizeof(float), 0);

    const int threads = 256;

    if (F == 16 && (E % 4) == 0) {
        int Eq = E / 4;
        int blocks = (Eq + threads - 1) / threads;
        scatter_sum_f16_q4<<<blocks, threads, 0, 0>>>(
            (const float4*)attrs, (const int4*)aidx, out, Eq, out_size);
    } else {
        int blocks = (E + threads - 1) / threads;
        scatter_sum_scalar<<<blocks, threads, 0, 0>>>(attrs, aidx, out, E, F, out_size);
    }
}